// round 4
// baseline (speedup 1.0000x reference)
#include <cuda_runtime.h>

// Problem constants
static const int BB  = 8;
static const int NN  = 20000;
static const int DD  = 64;
static const int DD2 = 128;
static const int RR  = 24;
static const int SS  = 3;
static const int EE  = 60000;
static const int KK  = 101;
static const int HL  = 50;
static const int FDIM = 192;   // D + 2D

// packed fp32x2 helpers (SASS FFMA2 path — 2x fp32 FMA throughput)
#define FMA_F32X2(d, a, b, c) \
    asm("fma.rn.f32x2 %0, %1, %2, %3;" : "=l"(d) : "l"(a), "l"(b), "l"(c))
#define PACKF2(d, lo, hi) \
    asm("mov.b64 %0, {%1, %2};" : "=l"(d) : "f"(lo), "f"(hi))
#define UNPACKF2(lo, hi, v) \
    asm("mov.b64 {%0, %1}, %2;" : "=f"(lo), "=f"(hi) : "l"(v))

// ---------------- scratch (device globals; no allocations allowed) ----------
__device__ float g_init[BB * NN * DD];
__device__ float g_xA[BB * NN * DD];
__device__ float g_xB[BB * NN * DD];
__device__ int   g_cnt_poi[SS][NN];
__device__ int   g_cnt_dst[SS][NN];
__device__ int   g_rowstart[SS][NN];
__device__ int   g_rowfill[SS][NN];
__device__ int   g_total[SS];
__device__ int   g_csr_src[SS][EE];
__device__ int   g_csr_et[SS][EE];
__device__ float g_relsum[SS][2][NN * DD];
__device__ float g_query[BB * DD];
__device__ float g_xseq[BB * HL * DD2];
__device__ float g_qkv[BB * HL * 3 * DD2];
__device__ float g_ao[BB * HL * DD2];
__device__ float g_h1[BB * HL * 4 * DD2];
__device__ float g_flabel[BB * DD2];

// ---------------- CSR build (batched over all S snapshots) -------------------
__global__ void k_zero_counts() {
    int s = blockIdx.y;
    int i = blockIdx.x * blockDim.x + threadIdx.x;
    if (i < NN) { g_cnt_poi[s][i] = 0; g_cnt_dst[s][i] = 0; g_rowfill[s][i] = 0; }
    if (i == 0) g_total[s] = 0;
}

__global__ void k_count(const int* __restrict__ src, const int* __restrict__ dst) {
    int s = blockIdx.y;
    int e = blockIdx.x * blockDim.x + threadIdx.x;
    if (e < EE) {
        atomicAdd(&g_cnt_poi[s][src[s * EE + e]], 1);
        atomicAdd(&g_cnt_poi[s][dst[s * EE + e]], 1);
        atomicAdd(&g_cnt_dst[s][dst[s * EE + e]], 1);
    }
}

// warp-aggregated contiguous range assignment (order-free)
__global__ void k_offsets() {
    int s = blockIdx.y;
    int n = blockIdx.x * blockDim.x + threadIdx.x;
    int lane = threadIdx.x & 31;
    int c = (n < NN) ? g_cnt_dst[s][n] : 0;
    int pre = c;
    #pragma unroll
    for (int off = 1; off < 32; off <<= 1) {
        int t = __shfl_up_sync(0xffffffffu, pre, off);
        if (lane >= off) pre += t;
    }
    int tot = __shfl_sync(0xffffffffu, pre, 31);
    int base = 0;
    if (lane == 31 && tot > 0) base = atomicAdd(&g_total[s], tot);
    base = __shfl_sync(0xffffffffu, base, 31);
    if (n < NN) g_rowstart[s][n] = base + pre - c;
}

__global__ void k_scatter(const int* __restrict__ src, const int* __restrict__ dst,
                          const int* __restrict__ et) {
    int s = blockIdx.y;
    int e = blockIdx.x * blockDim.x + threadIdx.x;
    if (e < EE) {
        int dn = dst[s * EE + e];
        int pos = g_rowstart[s][dn] + atomicAdd(&g_rowfill[s][dn], 1);
        g_csr_src[s][pos] = src[s * EE + e];
        g_csr_et[s][pos]  = et[s * EE + e];
    }
}

// per-node, per-layer sum of relation embeddings (batch-independent), all s
__global__ void k_relsum(const float* __restrict__ rel) {  // rel: [2, R, D]
    int s = blockIdx.y;
    int i = blockIdx.x * blockDim.x + threadIdx.x;  // NN*DD
    if (i >= NN * DD) return;
    int n = i >> 6, j = i & 63;
    int rs = g_rowstart[s][n], cnt = g_cnt_dst[s][n];
    float a0 = 0.f, a1 = 0.f;
    for (int p = rs; p < rs + cnt; p++) {
        int r = __ldg(&g_csr_et[s][p]);
        a0 += __ldg(&rel[r * DD + j]);
        a1 += __ldg(&rel[RR * DD + r * DD + j]);
    }
    g_relsum[s][0][i] = a0;
    g_relsum[s][1][i] = a1;
}

// ---------------- init (snapshot 0: single batch row) ------------------------
__global__ void k_init0(const float* __restrict__ poi) {
    int i = blockIdx.x * blockDim.x + threadIdx.x;
    if (i < NN * DD) {
        int n = i >> 6;
        g_init[i] = (float)g_cnt_poi[0][n] * poi[i];
    }
}

// gate: 32 nodes/block, 128 threads, f32x2 register-tile GEMM (K=64)
__global__ void k_gate_init(const float* __restrict__ poi,
                            const float* __restrict__ gW,
                            const float* __restrict__ gb, int prevBS, int s) {
    const int P = 36;
    __shared__ float s_in[DD * P];
    int n0 = blockIdx.x * 32;
    int b  = blockIdx.y;
    int tid = threadIdx.x;
    // gather prev state
    {
        int j = tid & 63, half = tid >> 6;
        for (int node = half; node < 32; node += 2) {
            int n = n0 + node;
            s_in[j * P + node] = g_xB[b * prevBS + n * DD + j];
        }
    }
    __syncthreads();
    int cg = tid & 15, ng = tid >> 4;      // cols cg*4.., nodes ng*4..
    unsigned long long acc[4][2];          // acc[c][pair]
    #pragma unroll
    for (int c = 0; c < 4; c++) {
        float bc = gb[cg * 4 + c];
        PACKF2(acc[c][0], bc, bc);
        acc[c][1] = acc[c][0];
    }
    for (int k = 0; k < DD; k++) {
        float4 w4 = __ldg((const float4*)&gW[k * DD + cg * 4]);
        float4 x4 = *(const float4*)&s_in[k * P + ng * 4];
        unsigned long long x01, x23, wd0, wd1, wd2, wd3;
        PACKF2(x01, x4.x, x4.y); PACKF2(x23, x4.z, x4.w);
        PACKF2(wd0, w4.x, w4.x); PACKF2(wd1, w4.y, w4.y);
        PACKF2(wd2, w4.z, w4.z); PACKF2(wd3, w4.w, w4.w);
        FMA_F32X2(acc[0][0], wd0, x01, acc[0][0]); FMA_F32X2(acc[0][1], wd0, x23, acc[0][1]);
        FMA_F32X2(acc[1][0], wd1, x01, acc[1][0]); FMA_F32X2(acc[1][1], wd1, x23, acc[1][1]);
        FMA_F32X2(acc[2][0], wd2, x01, acc[2][0]); FMA_F32X2(acc[2][1], wd2, x23, acc[2][1]);
        FMA_F32X2(acc[3][0], wd3, x01, acc[3][0]); FMA_F32X2(acc[3][1], wd3, x23, acc[3][1]);
    }
    #pragma unroll
    for (int p = 0; p < 2; p++) {
        float lo[4], hi[4];
        #pragma unroll
        for (int c = 0; c < 4; c++) UNPACKF2(lo[c], hi[c], acc[c][p]);
        #pragma unroll
        for (int e = 0; e < 2; e++) {
            int node = ng * 4 + p * 2 + e;
            int n = n0 + node;
            float cntf = (float)g_cnt_poi[s][n];
            float4 pv = __ldg((const float4*)&poi[n * DD + cg * 4]);
            float4 o;
            float* vv = e ? hi : lo;
            float g0 = 1.f / (1.f + __expf(-vv[0]));
            float g1 = 1.f / (1.f + __expf(-vv[1]));
            float g2 = 1.f / (1.f + __expf(-vv[2]));
            float g3 = 1.f / (1.f + __expf(-vv[3]));
            float p0 = s_in[(cg * 4 + 0) * P + node];
            float p1 = s_in[(cg * 4 + 1) * P + node];
            float p2 = s_in[(cg * 4 + 2) * P + node];
            float p3 = s_in[(cg * 4 + 3) * P + node];
            o.x = cntf * pv.x * g0 + (1.f - g0) * p0;
            o.y = cntf * pv.y * g1 + (1.f - g1) * p1;
            o.z = cntf * pv.z * g2 + (1.f - g2) * p2;
            o.w = cntf * pv.w * g3 + (1.f - g3) * p3;
            *(float4*)&g_init[(b * NN + n) * DD + cg * 4] = o;
        }
    }
}

// ---------------- fused GNN layer: gather + [agg|init] @ W + ReLU ------------
// 32 nodes/block, 128 threads, f32x2 register-tile GEMM (K=128)
__global__ void k_layer(int s, int layer,
                        const float* __restrict__ W,
                        const float* __restrict__ bias) {
    const int P = 36;
    __shared__ float s_in[2 * DD * P];
    int n0 = blockIdx.x * 32;
    int b  = blockIdx.y;
    int tid = threadIdx.x;
    {
        int j = tid & 63, half = tid >> 6;
        const float* xin = (layer == 0) ? g_init : g_xA;
        const float* xb = xin + b * NN * DD;
        const float* relsum = g_relsum[s][layer];
        const int* csr = g_csr_src[s];
        for (int node = half; node < 32; node += 2) {
            int n = n0 + node;
            int rs = g_rowstart[s][n], cnt = g_cnt_dst[s][n];
            float acc = __ldg(&relsum[n * DD + j]);
            for (int p = rs; p < rs + cnt; p++)
                acc += xb[__ldg(&csr[p]) * DD + j];
            s_in[j * P + node] = acc;
            s_in[(DD + j) * P + node] = g_init[(b * NN + n) * DD + j];
        }
    }
    __syncthreads();
    int cg = tid & 15, ng = tid >> 4;
    float* xout = (layer == 0) ? g_xA : g_xB;
    unsigned long long acc[4][2];
    #pragma unroll
    for (int c = 0; c < 4; c++) {
        float bc = bias[cg * 4 + c];
        PACKF2(acc[c][0], bc, bc);
        acc[c][1] = acc[c][0];
    }
    for (int k = 0; k < 2 * DD; k++) {
        float4 w4 = __ldg((const float4*)&W[k * DD + cg * 4]);
        float4 x4 = *(const float4*)&s_in[k * P + ng * 4];
        unsigned long long x01, x23, wd0, wd1, wd2, wd3;
        PACKF2(x01, x4.x, x4.y); PACKF2(x23, x4.z, x4.w);
        PACKF2(wd0, w4.x, w4.x); PACKF2(wd1, w4.y, w4.y);
        PACKF2(wd2, w4.z, w4.z); PACKF2(wd3, w4.w, w4.w);
        FMA_F32X2(acc[0][0], wd0, x01, acc[0][0]); FMA_F32X2(acc[0][1], wd0, x23, acc[0][1]);
        FMA_F32X2(acc[1][0], wd1, x01, acc[1][0]); FMA_F32X2(acc[1][1], wd1, x23, acc[1][1]);
        FMA_F32X2(acc[2][0], wd2, x01, acc[2][0]); FMA_F32X2(acc[2][1], wd2, x23, acc[2][1]);
        FMA_F32X2(acc[3][0], wd3, x01, acc[3][0]); FMA_F32X2(acc[3][1], wd3, x23, acc[3][1]);
    }
    #pragma unroll
    for (int p = 0; p < 2; p++) {
        float lo[4], hi[4];
        #pragma unroll
        for (int c = 0; c < 4; c++) UNPACKF2(lo[c], hi[c], acc[c][p]);
        int n_e = n0 + ng * 4 + p * 2;
        float4 v0, v1;
        v0.x = fmaxf(lo[0], 0.f); v0.y = fmaxf(lo[1], 0.f);
        v0.z = fmaxf(lo[2], 0.f); v0.w = fmaxf(lo[3], 0.f);
        v1.x = fmaxf(hi[0], 0.f); v1.y = fmaxf(hi[1], 0.f);
        v1.z = fmaxf(hi[2], 0.f); v1.w = fmaxf(hi[3], 0.f);
        *(float4*)&xout[(b * NN + n_e) * DD + cg * 4] = v0;
        *(float4*)&xout[(b * NN + n_e + 1) * DD + cg * 4] = v1;
    }
}

// ---------------- query handling ---------------------------------------------
__global__ void k_qinit(const float* __restrict__ qe, const int* __restrict__ ridx) {
    int tid = threadIdx.x;           // 512 = B*D
    int b = tid >> 6, d = tid & 63;
    g_query[tid] = qe[ridx[b] * DD + d];
}

__global__ void k_qupd(const float* __restrict__ temb, const int* __restrict__ gtime,
                       int s, const float* __restrict__ lw, const float* __restrict__ lb) {
    __shared__ float sq[BB * DD];
    int tid = threadIdx.x;           // 512
    int b = tid >> 6, d = tid & 63;
    int t = gtime[s];
    sq[tid] = g_query[tid] + temb[t * DD + d];
    __syncthreads();
    float acc = lb[d];
    #pragma unroll 8
    for (int k = 0; k < DD; k++) acc = fmaf(sq[b * DD + k], lw[k * DD + d], acc);
    g_query[tid] = acc;
}

// ---------------- sequence build + transformer -------------------------------
__global__ void k_xseq(const int* __restrict__ hp, const float* __restrict__ hte) {
    int row = blockIdx.x;            // 0..B*HL-1
    int b = row / HL;
    int j = threadIdx.x;             // 128
    int p = hp[row];
    float v = (j < DD) ? g_xB[(b * NN + p) * DD + j] : g_query[b * DD + (j - DD)];
    g_xseq[row * DD2 + j] = v + hte[row * DD2 + j];
}

__global__ void k_qkv(const float* __restrict__ Wqkv, int l) {
    __shared__ float sx[DD2];
    int row = blockIdx.x;
    int c = threadIdx.x;             // 384
    if (c < DD2) sx[c] = g_xseq[row * DD2 + c];
    __syncthreads();
    const float* W = Wqkv + l * DD2 * 3 * DD2;
    float acc = 0.f;
    #pragma unroll 8
    for (int k = 0; k < DD2; k++) acc = fmaf(sx[k], __ldg(&W[k * 384 + c]), acc);
    g_qkv[row * 384 + c] = acc;
}

__global__ void k_att() {
    const int PQ = 65;
    __shared__ float sq[HL * PQ];
    __shared__ float sk[HL * PQ];
    __shared__ float sv[HL * PQ];
    __shared__ float ss[HL * HL];
    int b = blockIdx.x, h = blockIdx.y;
    int tid = threadIdx.x;           // 256
    for (int i = tid; i < HL * DD; i += 256) {
        int t = i / DD, d = i & 63;
        int base = (b * HL + t) * 384 + h * 64 + d;
        sq[t * PQ + d] = g_qkv[base];
        sk[t * PQ + d] = g_qkv[base + 128];
        sv[t * PQ + d] = g_qkv[base + 256];
    }
    __syncthreads();
    for (int o = tid; o < HL * HL; o += 256) {
        int i = o / HL, jj = o % HL;
        float acc = 0.f;
        #pragma unroll 8
        for (int d = 0; d < 64; d++) acc = fmaf(sq[i * PQ + d], sk[jj * PQ + d], acc);
        ss[o] = acc * 0.125f;
    }
    __syncthreads();
    for (int i = tid; i < HL; i += 256) {
        float m = -1e30f;
        for (int jj = 0; jj < HL; jj++) m = fmaxf(m, ss[i * HL + jj]);
        float sum = 0.f;
        for (int jj = 0; jj < HL; jj++) { float e = __expf(ss[i * HL + jj] - m); ss[i * HL + jj] = e; sum += e; }
        float inv = 1.f / sum;
        for (int jj = 0; jj < HL; jj++) ss[i * HL + jj] *= inv;
    }
    __syncthreads();
    for (int o = tid; o < HL * DD; o += 256) {
        int i = o / DD, d = o & 63;
        float acc = 0.f;
        #pragma unroll 5
        for (int jj = 0; jj < HL; jj++) acc = fmaf(ss[i * HL + jj], sv[jj * PQ + d], acc);
        g_ao[(b * HL + i) * DD2 + h * 64 + d] = acc;
    }
}

__global__ void k_proj_ln(const float* __restrict__ Wo, const float* __restrict__ ln1, int l) {
    __shared__ float so[DD2];
    __shared__ float red[DD2];
    int row = blockIdx.x;
    int j = threadIdx.x;             // 128
    so[j] = g_ao[row * DD2 + j];
    __syncthreads();
    const float* W = Wo + l * DD2 * DD2;
    float acc = 0.f;
    #pragma unroll 8
    for (int k = 0; k < DD2; k++) acc = fmaf(so[k], __ldg(&W[k * DD2 + j]), acc);
    float v = g_xseq[row * DD2 + j] + acc;
    red[j] = v;
    __syncthreads();
    for (int off = 64; off > 0; off >>= 1) { if (j < off) red[j] += red[j + off]; __syncthreads(); }
    float mean = red[0] * (1.f / 128.f);
    __syncthreads();
    float dv = v - mean;
    red[j] = dv * dv;
    __syncthreads();
    for (int off = 64; off > 0; off >>= 1) { if (j < off) red[j] += red[j + off]; __syncthreads(); }
    float var = red[0] * (1.f / 128.f);
    const float* lnl = ln1 + l * 2 * DD2;
    g_xseq[row * DD2 + j] = dv * rsqrtf(var + 1e-5f) * lnl[j] + lnl[DD2 + j];
}

__global__ void k_ff1(const float* __restrict__ W1, const float* __restrict__ b1, int l) {
    __shared__ float sx[DD2];
    int row = blockIdx.x;
    int c = threadIdx.x;             // 512
    if (c < DD2) sx[c] = g_xseq[row * DD2 + c];
    __syncthreads();
    const float* W = W1 + l * DD2 * 512;
    float acc = b1[l * 512 + c];
    #pragma unroll 8
    for (int k = 0; k < DD2; k++) acc = fmaf(sx[k], __ldg(&W[k * 512 + c]), acc);
    g_h1[row * 512 + c] = fmaxf(acc, 0.f);
}

__global__ void k_ff2_ln(const float* __restrict__ W2, const float* __restrict__ b2,
                         const float* __restrict__ ln2, int l) {
    __shared__ float sh[512];
    __shared__ float red[DD2];
    int row = blockIdx.x;
    int j = threadIdx.x;             // 128
    for (int k = j; k < 512; k += 128) sh[k] = g_h1[row * 512 + k];
    __syncthreads();
    const float* W = W2 + l * 512 * DD2;
    float acc = b2[l * DD2 + j];
    #pragma unroll 8
    for (int k = 0; k < 512; k++) acc = fmaf(sh[k], __ldg(&W[k * DD2 + j]), acc);
    float v = g_xseq[row * DD2 + j] + acc;
    red[j] = v;
    __syncthreads();
    for (int off = 64; off > 0; off >>= 1) { if (j < off) red[j] += red[j + off]; __syncthreads(); }
    float mean = red[0] * (1.f / 128.f);
    __syncthreads();
    float dv = v - mean;
    red[j] = dv * dv;
    __syncthreads();
    for (int off = 64; off > 0; off >>= 1) { if (j < off) red[j] += red[j + off]; __syncthreads(); }
    float var = red[0] * (1.f / 128.f);
    const float* lnl = ln2 + l * 2 * DD2;
    g_xseq[row * DD2 + j] = dv * rsqrtf(var + 1e-5f) * lnl[j] + lnl[DD2 + j];
}

__global__ void k_flabel() {
    int b = blockIdx.x;
    int j = threadIdx.x;             // 128
    float s = 0.f;
    for (int t = 0; t < HL; t++) s += g_xseq[(b * HL + t) * DD2 + j];
    g_flabel[b * DD2 + j] = s * (1.f / (float)HL);
}

// ---------------- final scoring MLP -------------------------------------------
__global__ void k_score(const int* __restrict__ tidx,
                        const float* __restrict__ W1, const float* __restrict__ b1,
                        const float* __restrict__ W2, const float* __restrict__ b2,
                        float* __restrict__ out) {
    __shared__ float ft[FDIM];
    __shared__ float sh[256];
    int blk = blockIdx.x;
    int b = blk / KK;
    int j = threadIdx.x;             // 192
    int ti = tidx[blk];
    ft[j] = (j < DD) ? g_xB[(b * NN + ti) * DD + j] : g_flabel[b * DD2 + (j - DD)];
    if (j < 64) sh[192 + j] = 0.f;
    __syncthreads();
    float acc = b1[j];
    #pragma unroll 8
    for (int q = 0; q < FDIM; q++) acc = fmaf(ft[q], __ldg(&W1[q * FDIM + j]), acc);
    float h = fmaxf(acc, 0.f);
    sh[j] = h * W2[j];
    __syncthreads();
    for (int off = 128; off > 0; off >>= 1) { if (j < off) sh[j] += sh[j + off]; __syncthreads(); }
    if (j == 0) out[blk] = sh[0] + b2[0];
}

// ---------------- host launcher -------------------------------------------------
extern "C" void kernel_launch(void* const* d_in, const int* in_sizes, int n_in,
                              void* d_out, int out_size) {
    const float* poi   = (const float*)d_in[0];
    const float* qemb  = (const float*)d_in[1];
    const float* gateW = (const float*)d_in[2];
    const float* gateb = (const float*)d_in[3];
    const float* gnn_rel = (const float*)d_in[4];
    const float* gnn_W   = (const float*)d_in[5];
    const float* gnn_b   = (const float*)d_in[6];
    const float* gte  = (const float*)d_in[7];
    const float* glW  = (const float*)d_in[8];
    const float* glb  = (const float*)d_in[9];
    const float* Wqkv = (const float*)d_in[10];
    const float* Wo   = (const float*)d_in[11];
    const float* ln1  = (const float*)d_in[12];
    const float *W1, *b1, *W2, *b2, *ln2;
    if (in_sizes[13] == 2 * 2 * DD2) {       // dict order: ln2 right after ln1
        ln2 = (const float*)d_in[13];
        W1  = (const float*)d_in[14];
        b1  = (const float*)d_in[15];
        W2  = (const float*)d_in[16];
        b2  = (const float*)d_in[17];
    } else {                                 // signature order
        W1  = (const float*)d_in[13];
        b1  = (const float*)d_in[14];
        W2  = (const float*)d_in[15];
        b2  = (const float*)d_in[16];
        ln2 = (const float*)d_in[17];
    }
    const float* mW1 = (const float*)d_in[18];
    const float* mb1 = (const float*)d_in[19];
    const float* mW2 = (const float*)d_in[20];
    const float* mb2 = (const float*)d_in[21];
    const float* hte = (const float*)d_in[22];
    const int* esrc  = (const int*)d_in[23];
    const int* edst  = (const int*)d_in[24];
    const int* etyp  = (const int*)d_in[25];
    const int* ridx  = (const int*)d_in[27];
    const int* tidx  = (const int*)d_in[28];
    const int* hpoi  = (const int*)d_in[29];
    const int* gtime = (const int*)d_in[30];
    float* out = (float*)d_out;

    k_qinit<<<1, BB * DD>>>(qemb, ridx);

    // batched CSR for all snapshots
    k_zero_counts<<<dim3((NN + 255) / 256, SS), 256>>>();
    k_count<<<dim3((EE + 255) / 256, SS), 256>>>(esrc, edst);
    k_offsets<<<dim3((NN + 255) / 256, SS), 256>>>();
    k_scatter<<<dim3((EE + 255) / 256, SS), 256>>>(esrc, edst, etyp);
    k_relsum<<<dim3(NN * DD / 256, SS), 256>>>(gnn_rel);

    for (int s = 0; s < SS; s++) {
        int nb = (s == 0) ? 1 : BB;          // snapshot 0 is batch-invariant
        if (s == 0)
            k_init0<<<(NN * DD + 255) / 256, 256>>>(poi);
        else
            k_gate_init<<<dim3(NN / 32, BB), 128>>>(poi, gateW, gateb,
                                                    (s == 1) ? 0 : NN * DD, s);
        for (int l = 0; l < 2; l++) {
            k_layer<<<dim3(NN / 32, nb), 128>>>(s, l,
                                                gnn_W + l * 2 * DD * DD,
                                                gnn_b + l * DD);
        }
        k_qupd<<<1, BB * DD>>>(gte, gtime, s, glW, glb);
    }

    k_xseq<<<BB * HL, DD2>>>(hpoi, hte);
    for (int l = 0; l < 2; l++) {
        k_qkv<<<BB * HL, 3 * DD2>>>(Wqkv, l);
        k_att<<<dim3(BB, 2), 256>>>();
        k_proj_ln<<<BB * HL, DD2>>>(Wo, ln1, l);
        k_ff1<<<BB * HL, 4 * DD2>>>(W1, b1, l);
        k_ff2_ln<<<BB * HL, DD2>>>(W2, b2, ln2, l);
    }
    k_flabel<<<BB, DD2>>>();
    k_score<<<BB * KK, FDIM>>>(tidx, mW1, mb1, mW2, mb2, out);
}

// round 5
// speedup vs baseline: 1.3205x; 1.3205x over previous
#include <cuda_runtime.h>

// Problem constants
static const int BB  = 8;
static const int NN  = 20000;
static const int DD  = 64;
static const int DD2 = 128;
static const int RR  = 24;
static const int SS  = 3;
static const int EE  = 60000;
static const int KK  = 101;
static const int HL  = 50;
static const int FDIM = 192;   // D + 2D

// packed fp32x2 helpers (SASS FFMA2 path — 2x fp32 FMA throughput)
#define FMA_F32X2(d, a, b, c) \
    asm("fma.rn.f32x2 %0, %1, %2, %3;" : "=l"(d) : "l"(a), "l"(b), "l"(c))
#define PACKF2(d, lo, hi) \
    asm("mov.b64 %0, {%1, %2};" : "=l"(d) : "f"(lo), "f"(hi))
#define UNPACKF2(lo, hi, v) \
    asm("mov.b64 {%0, %1}, %2;" : "=f"(lo), "=f"(hi) : "l"(v))

// ---------------- scratch (device globals; no allocations allowed) ----------
__device__ float g_init[BB * NN * DD];
__device__ float g_xA[BB * NN * DD];
__device__ float g_xB[BB * NN * DD];
__device__ int   g_cnt_poi[SS][NN];
__device__ int   g_cnt_dst[SS][NN];
__device__ int   g_rowstart[SS][NN];
__device__ int   g_rowfill[SS][NN];
__device__ int   g_total[SS];
__device__ int   g_csr_src[SS][EE];
__device__ int   g_csr_et[SS][EE];
__device__ float g_relsum[SS][2][NN * DD];
__device__ float g_query[BB * DD];
__device__ float g_xseq[BB * HL * DD2];
__device__ float g_qkv[BB * HL * 3 * DD2];
__device__ float g_ao[BB * HL * DD2];
__device__ float g_h1[BB * HL * 4 * DD2];
__device__ float g_flabel[BB * DD2];

// ---------------- CSR build (batched over all S snapshots) -------------------
__global__ void k_zero_counts() {
    int s = blockIdx.y;
    int i = blockIdx.x * blockDim.x + threadIdx.x;
    if (i < NN) { g_cnt_poi[s][i] = 0; g_cnt_dst[s][i] = 0; g_rowfill[s][i] = 0; }
    if (i == 0) g_total[s] = 0;
}

__global__ void k_count(const int* __restrict__ src, const int* __restrict__ dst) {
    int s = blockIdx.y;
    int e = blockIdx.x * blockDim.x + threadIdx.x;
    if (e < EE) {
        atomicAdd(&g_cnt_poi[s][src[s * EE + e]], 1);
        atomicAdd(&g_cnt_poi[s][dst[s * EE + e]], 1);
        atomicAdd(&g_cnt_dst[s][dst[s * EE + e]], 1);
    }
}

// warp-aggregated contiguous range assignment (order-free)
__global__ void k_offsets() {
    int s = blockIdx.y;
    int n = blockIdx.x * blockDim.x + threadIdx.x;
    int lane = threadIdx.x & 31;
    int c = (n < NN) ? g_cnt_dst[s][n] : 0;
    int pre = c;
    #pragma unroll
    for (int off = 1; off < 32; off <<= 1) {
        int t = __shfl_up_sync(0xffffffffu, pre, off);
        if (lane >= off) pre += t;
    }
    int tot = __shfl_sync(0xffffffffu, pre, 31);
    int base = 0;
    if (lane == 31 && tot > 0) base = atomicAdd(&g_total[s], tot);
    base = __shfl_sync(0xffffffffu, base, 31);
    if (n < NN) g_rowstart[s][n] = base + pre - c;
}

__global__ void k_scatter(const int* __restrict__ src, const int* __restrict__ dst,
                          const int* __restrict__ et) {
    int s = blockIdx.y;
    int e = blockIdx.x * blockDim.x + threadIdx.x;
    if (e < EE) {
        int dn = dst[s * EE + e];
        int pos = g_rowstart[s][dn] + atomicAdd(&g_rowfill[s][dn], 1);
        g_csr_src[s][pos] = src[s * EE + e];
        g_csr_et[s][pos]  = et[s * EE + e];
    }
}

// per-node, per-layer sum of relation embeddings (batch-independent), all s
__global__ void k_relsum(const float* __restrict__ rel) {  // rel: [2, R, D]
    int s = blockIdx.y;
    int i = blockIdx.x * blockDim.x + threadIdx.x;  // NN*DD
    if (i >= NN * DD) return;
    int n = i >> 6, j = i & 63;
    int rs = g_rowstart[s][n], cnt = g_cnt_dst[s][n];
    float a0 = 0.f, a1 = 0.f;
    for (int p = rs; p < rs + cnt; p++) {
        int r = __ldg(&g_csr_et[s][p]);
        a0 += __ldg(&rel[r * DD + j]);
        a1 += __ldg(&rel[RR * DD + r * DD + j]);
    }
    g_relsum[s][0][i] = a0;
    g_relsum[s][1][i] = a1;
}

// ---------------- init (snapshot 0: single batch row) ------------------------
__global__ void k_init0(const float* __restrict__ poi) {
    int i = blockIdx.x * blockDim.x + threadIdx.x;
    if (i < NN * DD) {
        int n = i >> 6;
        g_init[i] = (float)g_cnt_poi[0][n] * poi[i];
    }
}

// 16 rows per block, 256 threads. prev output in g_xB; prevBS = 0 (b0 bcast) or NN*DD.
__global__ void k_gate_init(const float* __restrict__ poi,
                            const float* __restrict__ gW,
                            const float* __restrict__ gb, int prevBS, int s) {
    const int P = 20;
    __shared__ float s_in[DD * P];
    int n0 = blockIdx.x * 16;
    int b  = blockIdx.y;
    int tid = threadIdx.x;
    int j   = tid & 63;
    int gbk = tid >> 6;
    #pragma unroll
    for (int gi = 0; gi < 4; gi++) {
        int g = gbk * 4 + gi;
        int n = n0 + g;
        s_in[j * P + g] = g_xB[b * prevBS + n * DD + j];
    }
    __syncthreads();
    float bj = gb[j];
    unsigned long long acc01, acc23;
    PACKF2(acc01, bj, bj);
    acc23 = acc01;
    #pragma unroll 8
    for (int k = 0; k < DD; k++) {
        float w = __ldg(&gW[k * DD + j]);
        float4 a = *reinterpret_cast<const float4*>(&s_in[k * P + gbk * 4]);
        unsigned long long wd, x01, x23;
        PACKF2(wd, w, w);
        PACKF2(x01, a.x, a.y); PACKF2(x23, a.z, a.w);
        FMA_F32X2(acc01, wd, x01, acc01);
        FMA_F32X2(acc23, wd, x23, acc23);
    }
    float accs[4];
    UNPACKF2(accs[0], accs[1], acc01);
    UNPACKF2(accs[2], accs[3], acc23);
    #pragma unroll
    for (int gi = 0; gi < 4; gi++) {
        int g = gbk * 4 + gi;
        int n = n0 + g;
        float gt = 1.f / (1.f + __expf(-accs[gi]));
        float prv = s_in[j * P + g];
        float ione = (float)g_cnt_poi[s][n] * poi[n * DD + j];
        g_init[(b * NN + n) * DD + j] = ione * gt + (1.f - gt) * prv;
    }
}

// ---------------- fused GNN layer: gather + [agg|init] @ W + ReLU ------------
__global__ void k_layer(int s, int layer,
                        const float* __restrict__ W,
                        const float* __restrict__ bias) {
    const int P = 20;
    __shared__ float s_in[2 * DD * P];
    int n0 = blockIdx.x * 16;
    int b  = blockIdx.y;
    int tid = threadIdx.x;
    int j   = tid & 63;
    int gbk = tid >> 6;
    const float* xin  = (layer == 0) ? g_init : g_xA;
    float*       xout = (layer == 0) ? g_xA : g_xB;
    const float* relsum = g_relsum[s][layer];
    const int* csr = g_csr_src[s];
    const float* xb = xin + b * NN * DD;
    #pragma unroll
    for (int gi = 0; gi < 4; gi++) {
        int g = gbk * 4 + gi;
        int n = n0 + g;
        int rs = g_rowstart[s][n], cnt = g_cnt_dst[s][n];
        float acc = __ldg(&relsum[n * DD + j]);
        for (int p = rs; p < rs + cnt; p++)
            acc += xb[__ldg(&csr[p]) * DD + j];
        s_in[j * P + g] = acc;
        s_in[(DD + j) * P + g] = g_init[(b * NN + n) * DD + j];
    }
    __syncthreads();
    float bj = bias[j];
    unsigned long long acc01, acc23;
    PACKF2(acc01, bj, bj);
    acc23 = acc01;
    #pragma unroll 8
    for (int k = 0; k < 2 * DD; k++) {
        float w = __ldg(&W[k * DD + j]);
        float4 a = *reinterpret_cast<const float4*>(&s_in[k * P + gbk * 4]);
        unsigned long long wd, x01, x23;
        PACKF2(wd, w, w);
        PACKF2(x01, a.x, a.y); PACKF2(x23, a.z, a.w);
        FMA_F32X2(acc01, wd, x01, acc01);
        FMA_F32X2(acc23, wd, x23, acc23);
    }
    float accs[4];
    UNPACKF2(accs[0], accs[1], acc01);
    UNPACKF2(accs[2], accs[3], acc23);
    #pragma unroll
    for (int gi = 0; gi < 4; gi++) {
        int n = n0 + gbk * 4 + gi;
        xout[(b * NN + n) * DD + j] = fmaxf(accs[gi], 0.f);
    }
}

// ---------------- query handling ---------------------------------------------
__global__ void k_qinit(const float* __restrict__ qe, const int* __restrict__ ridx) {
    int tid = threadIdx.x;           // 512 = B*D
    int b = tid >> 6, d = tid & 63;
    g_query[tid] = qe[ridx[b] * DD + d];
}

__global__ void k_qupd(const float* __restrict__ temb, const int* __restrict__ gtime,
                       int s, const float* __restrict__ lw, const float* __restrict__ lb) {
    __shared__ float sq[BB * DD];
    int tid = threadIdx.x;           // 512
    int b = tid >> 6, d = tid & 63;
    int t = gtime[s];
    sq[tid] = g_query[tid] + temb[t * DD + d];
    __syncthreads();
    float acc = lb[d];
    #pragma unroll 8
    for (int k = 0; k < DD; k++) acc = fmaf(sq[b * DD + k], lw[k * DD + d], acc);
    g_query[tid] = acc;
}

// ---------------- sequence build + transformer -------------------------------
__global__ void k_xseq(const int* __restrict__ hp, const float* __restrict__ hte) {
    int row = blockIdx.x;            // 0..B*HL-1
    int b = row / HL;
    int j = threadIdx.x;             // 128
    int p = hp[row];
    float v = (j < DD) ? g_xB[(b * NN + p) * DD + j] : g_query[b * DD + (j - DD)];
    g_xseq[row * DD2 + j] = v + hte[row * DD2 + j];
}

__global__ void k_qkv(const float* __restrict__ Wqkv, int l) {
    __shared__ float sx[DD2];
    int row = blockIdx.x;
    int c = threadIdx.x;             // 384
    if (c < DD2) sx[c] = g_xseq[row * DD2 + c];
    __syncthreads();
    const float* W = Wqkv + l * DD2 * 3 * DD2;
    float acc = 0.f;
    #pragma unroll 8
    for (int k = 0; k < DD2; k++) acc = fmaf(sx[k], __ldg(&W[k * 384 + c]), acc);
    g_qkv[row * 384 + c] = acc;
}

__global__ void k_att() {
    const int PQ = 65;
    __shared__ float sq[HL * PQ];
    __shared__ float sk[HL * PQ];
    __shared__ float sv[HL * PQ];
    __shared__ float ss[HL * HL];
    int b = blockIdx.x, h = blockIdx.y;
    int tid = threadIdx.x;           // 256
    for (int i = tid; i < HL * DD; i += 256) {
        int t = i / DD, d = i & 63;
        int base = (b * HL + t) * 384 + h * 64 + d;
        sq[t * PQ + d] = g_qkv[base];
        sk[t * PQ + d] = g_qkv[base + 128];
        sv[t * PQ + d] = g_qkv[base + 256];
    }
    __syncthreads();
    for (int o = tid; o < HL * HL; o += 256) {
        int i = o / HL, jj = o % HL;
        float acc = 0.f;
        #pragma unroll 8
        for (int d = 0; d < 64; d++) acc = fmaf(sq[i * PQ + d], sk[jj * PQ + d], acc);
        ss[o] = acc * 0.125f;
    }
    __syncthreads();
    for (int i = tid; i < HL; i += 256) {
        float m = -1e30f;
        for (int jj = 0; jj < HL; jj++) m = fmaxf(m, ss[i * HL + jj]);
        float sum = 0.f;
        for (int jj = 0; jj < HL; jj++) { float e = __expf(ss[i * HL + jj] - m); ss[i * HL + jj] = e; sum += e; }
        float inv = 1.f / sum;
        for (int jj = 0; jj < HL; jj++) ss[i * HL + jj] *= inv;
    }
    __syncthreads();
    for (int o = tid; o < HL * DD; o += 256) {
        int i = o / DD, d = o & 63;
        float acc = 0.f;
        #pragma unroll 5
        for (int jj = 0; jj < HL; jj++) acc = fmaf(ss[i * HL + jj], sv[jj * PQ + d], acc);
        g_ao[(b * HL + i) * DD2 + h * 64 + d] = acc;
    }
}

__global__ void k_proj_ln(const float* __restrict__ Wo, const float* __restrict__ ln1, int l) {
    __shared__ float so[DD2];
    __shared__ float red[DD2];
    int row = blockIdx.x;
    int j = threadIdx.x;             // 128
    so[j] = g_ao[row * DD2 + j];
    __syncthreads();
    const float* W = Wo + l * DD2 * DD2;
    float acc = 0.f;
    #pragma unroll 8
    for (int k = 0; k < DD2; k++) acc = fmaf(so[k], __ldg(&W[k * DD2 + j]), acc);
    float v = g_xseq[row * DD2 + j] + acc;
    red[j] = v;
    __syncthreads();
    for (int off = 64; off > 0; off >>= 1) { if (j < off) red[j] += red[j + off]; __syncthreads(); }
    float mean = red[0] * (1.f / 128.f);
    __syncthreads();
    float dv = v - mean;
    red[j] = dv * dv;
    __syncthreads();
    for (int off = 64; off > 0; off >>= 1) { if (j < off) red[j] += red[j + off]; __syncthreads(); }
    float var = red[0] * (1.f / 128.f);
    const float* lnl = ln1 + l * 2 * DD2;
    g_xseq[row * DD2 + j] = dv * rsqrtf(var + 1e-5f) * lnl[j] + lnl[DD2 + j];
}

__global__ void k_ff1(const float* __restrict__ W1, const float* __restrict__ b1, int l) {
    __shared__ float sx[DD2];
    int row = blockIdx.x;
    int c = threadIdx.x;             // 512
    if (c < DD2) sx[c] = g_xseq[row * DD2 + c];
    __syncthreads();
    const float* W = W1 + l * DD2 * 512;
    float acc = b1[l * 512 + c];
    #pragma unroll 8
    for (int k = 0; k < DD2; k++) acc = fmaf(sx[k], __ldg(&W[k * 512 + c]), acc);
    g_h1[row * 512 + c] = fmaxf(acc, 0.f);
}

__global__ void k_ff2_ln(const float* __restrict__ W2, const float* __restrict__ b2,
                         const float* __restrict__ ln2, int l) {
    __shared__ float sh[512];
    __shared__ float red[DD2];
    int row = blockIdx.x;
    int j = threadIdx.x;             // 128
    for (int k = j; k < 512; k += 128) sh[k] = g_h1[row * 512 + k];
    __syncthreads();
    const float* W = W2 + l * 512 * DD2;
    float acc = b2[l * DD2 + j];
    #pragma unroll 8
    for (int k = 0; k < 512; k++) acc = fmaf(sh[k], __ldg(&W[k * DD2 + j]), acc);
    float v = g_xseq[row * DD2 + j] + acc;
    red[j] = v;
    __syncthreads();
    for (int off = 64; off > 0; off >>= 1) { if (j < off) red[j] += red[j + off]; __syncthreads(); }
    float mean = red[0] * (1.f / 128.f);
    __syncthreads();
    float dv = v - mean;
    red[j] = dv * dv;
    __syncthreads();
    for (int off = 64; off > 0; off >>= 1) { if (j < off) red[j] += red[j + off]; __syncthreads(); }
    float var = red[0] * (1.f / 128.f);
    const float* lnl = ln2 + l * 2 * DD2;
    g_xseq[row * DD2 + j] = dv * rsqrtf(var + 1e-5f) * lnl[j] + lnl[DD2 + j];
}

__global__ void k_flabel() {
    int b = blockIdx.x;
    int j = threadIdx.x;             // 128
    float s = 0.f;
    for (int t = 0; t < HL; t++) s += g_xseq[(b * HL + t) * DD2 + j];
    g_flabel[b * DD2 + j] = s * (1.f / (float)HL);
}

// ---------------- final scoring MLP -------------------------------------------
__global__ void k_score(const int* __restrict__ tidx,
                        const float* __restrict__ W1, const float* __restrict__ b1,
                        const float* __restrict__ W2, const float* __restrict__ b2,
                        float* __restrict__ out) {
    __shared__ float ft[FDIM];
    __shared__ float sh[256];
    int blk = blockIdx.x;
    int b = blk / KK;
    int j = threadIdx.x;             // 192
    int ti = tidx[blk];
    ft[j] = (j < DD) ? g_xB[(b * NN + ti) * DD + j] : g_flabel[b * DD2 + (j - DD)];
    if (j < 64) sh[192 + j] = 0.f;
    __syncthreads();
    float acc = b1[j];
    #pragma unroll 8
    for (int q = 0; q < FDIM; q++) acc = fmaf(ft[q], __ldg(&W1[q * FDIM + j]), acc);
    float h = fmaxf(acc, 0.f);
    sh[j] = h * W2[j];
    __syncthreads();
    for (int off = 128; off > 0; off >>= 1) { if (j < off) sh[j] += sh[j + off]; __syncthreads(); }
    if (j == 0) out[blk] = sh[0] + b2[0];
}

// ---------------- host launcher -------------------------------------------------
extern "C" void kernel_launch(void* const* d_in, const int* in_sizes, int n_in,
                              void* d_out, int out_size) {
    const float* poi   = (const float*)d_in[0];
    const float* qemb  = (const float*)d_in[1];
    const float* gateW = (const float*)d_in[2];
    const float* gateb = (const float*)d_in[3];
    const float* gnn_rel = (const float*)d_in[4];
    const float* gnn_W   = (const float*)d_in[5];
    const float* gnn_b   = (const float*)d_in[6];
    const float* gte  = (const float*)d_in[7];
    const float* glW  = (const float*)d_in[8];
    const float* glb  = (const float*)d_in[9];
    const float* Wqkv = (const float*)d_in[10];
    const float* Wo   = (const float*)d_in[11];
    const float* ln1  = (const float*)d_in[12];
    const float *W1, *b1, *W2, *b2, *ln2;
    if (in_sizes[13] == 2 * 2 * DD2) {       // dict order: ln2 right after ln1
        ln2 = (const float*)d_in[13];
        W1  = (const float*)d_in[14];
        b1  = (const float*)d_in[15];
        W2  = (const float*)d_in[16];
        b2  = (const float*)d_in[17];
    } else {                                 // signature order
        W1  = (const float*)d_in[13];
        b1  = (const float*)d_in[14];
        W2  = (const float*)d_in[15];
        b2  = (const float*)d_in[16];
        ln2 = (const float*)d_in[17];
    }
    const float* mW1 = (const float*)d_in[18];
    const float* mb1 = (const float*)d_in[19];
    const float* mW2 = (const float*)d_in[20];
    const float* mb2 = (const float*)d_in[21];
    const float* hte = (const float*)d_in[22];
    const int* esrc  = (const int*)d_in[23];
    const int* edst  = (const int*)d_in[24];
    const int* etyp  = (const int*)d_in[25];
    const int* ridx  = (const int*)d_in[27];
    const int* tidx  = (const int*)d_in[28];
    const int* hpoi  = (const int*)d_in[29];
    const int* gtime = (const int*)d_in[30];
    float* out = (float*)d_out;

    k_qinit<<<1, BB * DD>>>(qemb, ridx);

    // batched CSR for all snapshots
    k_zero_counts<<<dim3((NN + 255) / 256, SS), 256>>>();
    k_count<<<dim3((EE + 255) / 256, SS), 256>>>(esrc, edst);
    k_offsets<<<dim3((NN + 255) / 256, SS), 256>>>();
    k_scatter<<<dim3((EE + 255) / 256, SS), 256>>>(esrc, edst, etyp);
    k_relsum<<<dim3(NN * DD / 256, SS), 256>>>(gnn_rel);

    for (int s = 0; s < SS; s++) {
        int nb = (s == 0) ? 1 : BB;          // snapshot 0 is batch-invariant
        if (s == 0)
            k_init0<<<(NN * DD + 255) / 256, 256>>>(poi);
        else
            k_gate_init<<<dim3(NN / 16, BB), 256>>>(poi, gateW, gateb,
                                                    (s == 1) ? 0 : NN * DD, s);
        for (int l = 0; l < 2; l++) {
            k_layer<<<dim3(NN / 16, nb), 256>>>(s, l,
                                                gnn_W + l * 2 * DD * DD,
                                                gnn_b + l * DD);
        }
        k_qupd<<<1, BB * DD>>>(gte, gtime, s, glW, glb);
    }

    k_xseq<<<BB * HL, DD2>>>(hpoi, hte);
    for (int l = 0; l < 2; l++) {
        k_qkv<<<BB * HL, 3 * DD2>>>(Wqkv, l);
        k_att<<<dim3(BB, 2), 256>>>();
        k_proj_ln<<<BB * HL, DD2>>>(Wo, ln1, l);
        k_ff1<<<BB * HL, 4 * DD2>>>(W1, b1, l);
        k_ff2_ln<<<BB * HL, DD2>>>(W2, b2, ln2, l);
    }
    k_flabel<<<BB, DD2>>>();
    k_score<<<BB * KK, FDIM>>>(tidx, mW1, mb1, mW2, mb2, out);
}